// round 1
// baseline (speedup 1.0000x reference)
#include <cuda_runtime.h>
#include <cuda_bf16.h>
#include <math.h>

// Problem constants (fixed shapes from reference)
#define NN 100000
#define EE 1600000
#define ET (EE + NN)       // edges + self loops
#define D  128
#define HEADS 4
#define CH 32
#define NEG_SLOPE 0.2f

// ---------------- scratch (device globals; no runtime allocation) ------------
__device__ float g_bufA[NN * D];      // GEMM output / agg input (per layer)
__device__ float g_bufB[NN * D];      // relu(h1)
__device__ float g_xr[NN * D];        // x @ Wr
__device__ float g_ss[NN * HEADS];    // per-node src scores
__device__ float g_sd[NN * HEADS];    // per-node dst scores
__device__ int   g_deg[NN];
__device__ int   g_offs[NN + 1];
__device__ int   g_cursor[NN];
__device__ int   g_sorted_src[ET];
__device__ int   g_idx64;             // 1 if edge_index is int64, 0 if int32

// ---------------- edge index dtype detection ---------------------------------
__global__ void detect_kernel(const unsigned int* __restrict__ w) {
    if (threadIdx.x == 0 && blockIdx.x == 0) {
        int all0 = 1;
        for (int i = 0; i < 256; ++i) {
            if (w[2 * i + 1] != 0u) { all0 = 0; break; }
        }
        g_idx64 = all0;
    }
}

__device__ __forceinline__ int edge_val(const void* ei, long long idx) {
    if (g_idx64) return (int)((const long long*)ei)[idx];
    return ((const int*)ei)[idx];
}

// ---------------- counting sort by destination --------------------------------
__global__ void init_deg_kernel() {
    int i = blockIdx.x * blockDim.x + threadIdx.x;
    if (i < NN) g_deg[i] = 1;   // self loop
}

__global__ void count_kernel(const void* __restrict__ ei) {
    int i = blockIdx.x * blockDim.x + threadIdx.x;
    if (i >= EE) return;
    int d = edge_val(ei, (long long)EE + i);
    atomicAdd(&g_deg[d], 1);
}

__global__ void scan_kernel() {
    __shared__ int sums[1024];
    const int T = 1024;
    int tid = threadIdx.x;
    const int chunk = (NN + T - 1) / T;   // 98
    int start = tid * chunk;
    int local = 0;
    for (int i = 0; i < chunk; ++i) {
        int idx = start + i;
        if (idx < NN) local += g_deg[idx];
    }
    sums[tid] = local;
    __syncthreads();
    // inclusive Hillis-Steele
    for (int off = 1; off < T; off <<= 1) {
        int v = 0;
        if (tid >= off) v = sums[tid - off];
        __syncthreads();
        sums[tid] += v;
        __syncthreads();
    }
    int run = (tid == 0) ? 0 : sums[tid - 1];
    for (int i = 0; i < chunk; ++i) {
        int idx = start + i;
        if (idx < NN) {
            g_offs[idx]   = run;
            g_cursor[idx] = run;
            run += g_deg[idx];
        }
    }
    if (tid == T - 1) g_offs[NN] = run;   // = ET
}

__global__ void scatter_kernel(const void* __restrict__ ei) {
    int i = blockIdx.x * blockDim.x + threadIdx.x;
    if (i >= ET) return;
    int s, d;
    if (i < EE) {
        s = edge_val(ei, i);
        d = edge_val(ei, (long long)EE + i);
    } else {
        s = d = i - EE;   // self loop
    }
    int pos = atomicAdd(&g_cursor[d], 1);
    g_sorted_src[pos] = s;
}

// ---------------- GEMM (N x 128) @ (128 x 128) with fused attention scores ---
// block: 256 threads = 8 warps; tile: 64 rows x 128 cols; thread: 8 rows x 4 cols
template<bool SCORES>
__global__ void __launch_bounds__(256) gemm128_kernel(
    const float* __restrict__ A,
    const float* __restrict__ W,
    const float* __restrict__ a_src,
    const float* __restrict__ a_dst,
    float* __restrict__ out,
    float* __restrict__ ssrc,
    float* __restrict__ sdst)
{
    __shared__ float xT[32][65];    // transposed x chunk, padded
    __shared__ float Ws[32][128];   // W chunk

    int tid = threadIdx.x;
    int ty = tid >> 5;    // warp id 0..7 -> row group
    int tx = tid & 31;    // lane -> col group (4 cols)
    int row0 = blockIdx.x * 64;

    float acc[8][4];
#pragma unroll
    for (int i = 0; i < 8; ++i)
#pragma unroll
        for (int j = 0; j < 4; ++j) acc[i][j] = 0.f;

    for (int kc = 0; kc < D; kc += 32) {
        // load x chunk (64 rows x 32 k), transposed into smem
#pragma unroll
        for (int it = 0; it < 2; ++it) {
            int idx4 = tid + it * 256;      // 0..511
            int r  = idx4 >> 3;             // 0..63
            int k4 = idx4 & 7;              // 0..7
            int row = row0 + r;
            float4 v = make_float4(0.f, 0.f, 0.f, 0.f);
            if (row < NN) v = *(const float4*)&A[(long long)row * D + kc + k4 * 4];
            xT[k4 * 4 + 0][r] = v.x;
            xT[k4 * 4 + 1][r] = v.y;
            xT[k4 * 4 + 2][r] = v.z;
            xT[k4 * 4 + 3][r] = v.w;
        }
        // load W chunk (32 k x 128 c)
#pragma unroll
        for (int it = 0; it < 4; ++it) {
            int idx4 = tid + it * 256;      // 0..1023
            int kr = idx4 >> 5;             // 0..31
            int c4 = idx4 & 31;
            float4 v = *(const float4*)&W[(kc + kr) * D + c4 * 4];
            *(float4*)&Ws[kr][c4 * 4] = v;
        }
        __syncthreads();
#pragma unroll
        for (int k = 0; k < 32; ++k) {
            float4 bv = *(const float4*)&Ws[k][tx * 4];
#pragma unroll
            for (int i = 0; i < 8; ++i) {
                float a = xT[k][ty * 8 + i];
                acc[i][0] += a * bv.x;
                acc[i][1] += a * bv.y;
                acc[i][2] += a * bv.z;
                acc[i][3] += a * bv.w;
            }
        }
        __syncthreads();
    }

    int head = tx >> 3;
    float asv[4], adv[4];
    if (SCORES) {
#pragma unroll
        for (int j = 0; j < 4; ++j) {
            asv[j] = a_src[head * CH + (tx & 7) * 4 + j];
            adv[j] = a_dst[head * CH + (tx & 7) * 4 + j];
        }
    }
#pragma unroll
    for (int i = 0; i < 8; ++i) {
        int row = row0 + ty * 8 + i;
        if (row < NN) {
            *(float4*)&out[(long long)row * D + tx * 4] =
                make_float4(acc[i][0], acc[i][1], acc[i][2], acc[i][3]);
        }
        if (SCORES) {
            float su = acc[i][0] * asv[0] + acc[i][1] * asv[1] +
                       acc[i][2] * asv[2] + acc[i][3] * asv[3];
            float du = acc[i][0] * adv[0] + acc[i][1] * adv[1] +
                       acc[i][2] * adv[2] + acc[i][3] * adv[3];
            su += __shfl_xor_sync(0xffffffffu, su, 4);
            su += __shfl_xor_sync(0xffffffffu, su, 2);
            su += __shfl_xor_sync(0xffffffffu, su, 1);
            du += __shfl_xor_sync(0xffffffffu, du, 4);
            du += __shfl_xor_sync(0xffffffffu, du, 2);
            du += __shfl_xor_sync(0xffffffffu, du, 1);
            if (row < NN && (tx & 7) == 0) {
                ssrc[row * HEADS + head] = su;
                sdst[row * HEADS + head] = du;
            }
        }
    }
}

// ---------------- per-destination softmax + aggregation ----------------------
// one warp per destination node
__device__ __forceinline__ float lrelu(float v) {
    return v > 0.f ? v : NEG_SLOPE * v;
}

template<int LAYER>
__global__ void __launch_bounds__(256) agg_kernel(
    const float* __restrict__ h,     // [N,128] source features
    const float* __restrict__ ss,    // [N,4]
    const float* __restrict__ sd,    // [N,4]
    const float* __restrict__ bias,  // [128]
    float* __restrict__ out,         // [N,128]
    const float* __restrict__ xr,    // [N,128] residual (layer 2)
    const float* __restrict__ br)    // [128]   residual bias (layer 2)
{
    int warp = (blockIdx.x * blockDim.x + threadIdx.x) >> 5;
    int lane = threadIdx.x & 31;
    if (warp >= NN) return;
    int n = warp;
    int begin = g_offs[n], end = g_offs[n + 1];

    float4 sdv = *(const float4*)&sd[n * HEADS];

    // pass 1: per-head max (lane-strided)
    float m0 = -1e30f, m1 = -1e30f, m2 = -1e30f, m3 = -1e30f;
    for (int e = begin + lane; e < end; e += 32) {
        int s = g_sorted_src[e];
        float4 sv = *(const float4*)&ss[s * HEADS];
        m0 = fmaxf(m0, lrelu(sv.x + sdv.x));
        m1 = fmaxf(m1, lrelu(sv.y + sdv.y));
        m2 = fmaxf(m2, lrelu(sv.z + sdv.z));
        m3 = fmaxf(m3, lrelu(sv.w + sdv.w));
    }
#pragma unroll
    for (int off = 16; off; off >>= 1) {
        m0 = fmaxf(m0, __shfl_xor_sync(0xffffffffu, m0, off));
        m1 = fmaxf(m1, __shfl_xor_sync(0xffffffffu, m1, off));
        m2 = fmaxf(m2, __shfl_xor_sync(0xffffffffu, m2, off));
        m3 = fmaxf(m3, __shfl_xor_sync(0xffffffffu, m3, off));
    }

    // pass 2: per-head denom
    float d0 = 0.f, d1 = 0.f, d2 = 0.f, d3 = 0.f;
    for (int e = begin + lane; e < end; e += 32) {
        int s = g_sorted_src[e];
        float4 sv = *(const float4*)&ss[s * HEADS];
        d0 += expf(lrelu(sv.x + sdv.x) - m0);
        d1 += expf(lrelu(sv.y + sdv.y) - m1);
        d2 += expf(lrelu(sv.z + sdv.z) - m2);
        d3 += expf(lrelu(sv.w + sdv.w) - m3);
    }
#pragma unroll
    for (int off = 16; off; off >>= 1) {
        d0 += __shfl_xor_sync(0xffffffffu, d0, off);
        d1 += __shfl_xor_sync(0xffffffffu, d1, off);
        d2 += __shfl_xor_sync(0xffffffffu, d2, off);
        d3 += __shfl_xor_sync(0xffffffffu, d3, off);
    }

    // pass 3: weighted gather; lane owns 4 channels
    int hd = lane >> 3;                 // head for this lane's channels
    int c0 = lane * 4;
    float mh  = (hd == 0) ? m0 : (hd == 1) ? m1 : (hd == 2) ? m2 : m3;
    float dh  = (hd == 0) ? d0 : (hd == 1) ? d1 : (hd == 2) ? d2 : d3;
    float sdh = (hd == 0) ? sdv.x : (hd == 1) ? sdv.y : (hd == 2) ? sdv.z : sdv.w;
    float inv_dh = 1.f / dh;

    float ax = 0.f, ay = 0.f, az = 0.f, aw = 0.f;
    for (int e = begin; e < end; ++e) {
        int s = g_sorted_src[e];
        float el = lrelu(ss[s * HEADS + hd] + sdh);
        float alpha = expf(el - mh) * inv_dh;
        float4 hv = *(const float4*)&h[(long long)s * D + c0];
        ax += alpha * hv.x;
        ay += alpha * hv.y;
        az += alpha * hv.z;
        aw += alpha * hv.w;
    }

    float4 b = *(const float4*)&bias[c0];
    if (LAYER == 1) {
        float4 o = make_float4(fmaxf(ax + b.x, 0.f), fmaxf(ay + b.y, 0.f),
                               fmaxf(az + b.z, 0.f), fmaxf(aw + b.w, 0.f));
        *(float4*)&out[(long long)n * D + c0] = o;
    } else {
        float4 r  = *(const float4*)&xr[(long long)n * D + c0];
        float4 bb = *(const float4*)&br[c0];
        float4 o = make_float4(ax + b.x + r.x + bb.x, ay + b.y + r.y + bb.y,
                               az + b.z + r.z + bb.z, aw + b.w + r.w + bb.w);
        *(float4*)&out[(long long)n * D + c0] = o;
    }
}

// ---------------- launch ------------------------------------------------------
extern "C" void kernel_launch(void* const* d_in, const int* in_sizes, int n_in,
                              void* d_out, int out_size) {
    const float* x    = (const float*)d_in[0];
    const void*  ei   = d_in[1];
    const float* W1   = (const float*)d_in[2];
    const float* a1s  = (const float*)d_in[3];
    const float* a1d  = (const float*)d_in[4];
    const float* b1   = (const float*)d_in[5];
    const float* W2   = (const float*)d_in[6];
    const float* a2s  = (const float*)d_in[7];
    const float* a2d  = (const float*)d_in[8];
    const float* b2   = (const float*)d_in[9];
    const float* Wr   = (const float*)d_in[10];
    const float* br   = (const float*)d_in[11];
    float* out = (float*)d_out;

    float* bufA; cudaGetSymbolAddress((void**)&bufA, g_bufA);
    float* bufB; cudaGetSymbolAddress((void**)&bufB, g_bufB);
    float* xr;   cudaGetSymbolAddress((void**)&xr, g_xr);
    float* ssp;  cudaGetSymbolAddress((void**)&ssp, g_ss);
    float* sdp;  cudaGetSymbolAddress((void**)&sdp, g_sd);

    // edge preprocessing (counting sort by destination)
    detect_kernel<<<1, 32>>>((const unsigned int*)ei);
    init_deg_kernel<<<(NN + 255) / 256, 256>>>();
    count_kernel<<<(EE + 255) / 256, 256>>>(ei);
    scan_kernel<<<1, 1024>>>();
    scatter_kernel<<<(ET + 255) / 256, 256>>>(ei);

    const int gemm_grid = (NN + 63) / 64;
    // layer 1 transform + scores
    gemm128_kernel<true><<<gemm_grid, 256>>>(x, W1, a1s, a1d, bufA, ssp, sdp);
    // residual transform
    gemm128_kernel<false><<<gemm_grid, 256>>>(x, Wr, nullptr, nullptr, xr, nullptr, nullptr);
    // layer 1 aggregation -> relu(h1)
    agg_kernel<1><<<(NN + 7) / 8, 256>>>(bufA, ssp, sdp, b1, bufB, nullptr, nullptr);
    // layer 2 transform + scores
    gemm128_kernel<true><<<gemm_grid, 256>>>(bufB, W2, a2s, a2d, bufA, ssp, sdp);
    // layer 2 aggregation + residual -> out
    agg_kernel<2><<<(NN + 7) / 8, 256>>>(bufA, ssp, sdp, b2, out, xr, br);
}

// round 2
// speedup vs baseline: 1.3757x; 1.3757x over previous
#include <cuda_runtime.h>
#include <cuda_bf16.h>
#include <math.h>
#include <stdint.h>

#define NN 100000
#define EE 1600000
#define ET (EE + NN)
#define D  128
#define HEADS 4
#define CH 32
#define NEG_SLOPE 0.2f
#define CAP 128                 // per-node cached-edge cap (Poisson(17) => never exceeded)
#define NB_SCAN ((NN + 1023) / 1024)   // 98

// ---------------- scratch ------------------------------------------------------
__device__ float g_bufA[NN * D];
__device__ float g_bufB[NN * D];
__device__ float g_xr[NN * D];
__device__ float g_ss[NN * HEADS];
__device__ float g_sd[NN * HEADS];
__device__ int   g_deg[NN];
__device__ int   g_offs[NN + 1];
__device__ int   g_cursor[NN];
__device__ int   g_sorted_src[ET];
__device__ int   g_bsum[NB_SCAN];
__device__ int   g_bpre[NB_SCAN];
__device__ int   g_idx64;

// ---------------- edge dtype detection ----------------------------------------
__global__ void detect_kernel(const unsigned int* __restrict__ w) {
    if (threadIdx.x == 0 && blockIdx.x == 0) {
        int all0 = 1;
        for (int i = 0; i < 256; ++i)
            if (w[2 * i + 1] != 0u) { all0 = 0; break; }
        g_idx64 = all0;
    }
}
__device__ __forceinline__ int edge_val(const void* ei, long long idx) {
    if (g_idx64) return (int)((const long long*)ei)[idx];
    return ((const int*)ei)[idx];
}

// ---------------- counting sort -------------------------------------------------
__global__ void init_deg_kernel() {
    int i = blockIdx.x * blockDim.x + threadIdx.x;
    if (i < NN) g_deg[i] = 1;
}
__global__ void count_kernel(const void* __restrict__ ei) {
    int i = blockIdx.x * blockDim.x + threadIdx.x;
    if (i >= EE) return;
    atomicAdd(&g_deg[edge_val(ei, (long long)EE + i)], 1);
}

// scan k1: per-block (1024 elems) reduction
__global__ void __launch_bounds__(256) scan_k1() {
    __shared__ int sm[256];
    int b = blockIdx.x, tid = threadIdx.x;
    int base = b * 1024 + tid * 4;
    int s = 0;
#pragma unroll
    for (int j = 0; j < 4; ++j) {
        int idx = base + j;
        if (idx < NN) s += g_deg[idx];
    }
    sm[tid] = s;
    __syncthreads();
    for (int off = 128; off; off >>= 1) {
        if (tid < off) sm[tid] += sm[tid + off];
        __syncthreads();
    }
    if (tid == 0) g_bsum[b] = sm[0];
}

// scan k2: exclusive scan of 98 block sums
__global__ void scan_k2() {
    __shared__ int sm[128];
    int tid = threadIdx.x;
    sm[tid] = (tid < NB_SCAN) ? g_bsum[tid] : 0;
    __syncthreads();
    for (int off = 1; off < 128; off <<= 1) {
        int v = (tid >= off) ? sm[tid - off] : 0;
        __syncthreads();
        sm[tid] += v;
        __syncthreads();
    }
    if (tid < NB_SCAN) g_bpre[tid] = (tid == 0) ? 0 : sm[tid - 1];
    if (tid == 0) g_offs[NN] = ET;   // total degree is always E + N
}

// scan k3: per-block exclusive scan + global offset
__global__ void __launch_bounds__(256) scan_k3() {
    __shared__ int sm[256];
    int b = blockIdx.x, tid = threadIdx.x;
    int base = b * 1024 + tid * 4;
    int v[4];
#pragma unroll
    for (int j = 0; j < 4; ++j) {
        int idx = base + j;
        v[j] = (idx < NN) ? g_deg[idx] : 0;
    }
    int tot = v[0] + v[1] + v[2] + v[3];
    sm[tid] = tot;
    __syncthreads();
    for (int off = 1; off < 256; off <<= 1) {
        int x = (tid >= off) ? sm[tid - off] : 0;
        __syncthreads();
        sm[tid] += x;
        __syncthreads();
    }
    int run = g_bpre[b] + ((tid == 0) ? 0 : sm[tid - 1]);
#pragma unroll
    for (int j = 0; j < 4; ++j) {
        int idx = base + j;
        if (idx < NN) {
            g_offs[idx]   = run;
            g_cursor[idx] = run;
            run += v[j];
        }
    }
}

__global__ void scatter_kernel(const void* __restrict__ ei) {
    int i = blockIdx.x * blockDim.x + threadIdx.x;
    if (i >= ET) return;
    int s, d;
    if (i < EE) {
        s = edge_val(ei, i);
        d = edge_val(ei, (long long)EE + i);
    } else {
        s = d = i - EE;
    }
    int pos = atomicAdd(&g_cursor[d], 1);
    g_sorted_src[pos] = s;
}

// ---------------- tf32 tensor-core GEMM ----------------------------------------
__device__ __forceinline__ float to_tf32(float x) {
    uint32_t u;
    asm("cvt.rna.tf32.f32 %0, %1;" : "=r"(u) : "f"(x));
    return __uint_as_float(u);
}

#define MMA_TF32(c, av, bv)                                                  \
    asm volatile(                                                            \
        "mma.sync.aligned.m16n8k8.row.col.f32.tf32.tf32.f32 "                \
        "{%0,%1,%2,%3},{%4,%5,%6,%7},{%8,%9},{%0,%1,%2,%3};"                 \
        : "+f"((c)[0]), "+f"((c)[1]), "+f"((c)[2]), "+f"((c)[3])             \
        : "r"((av)[0]), "r"((av)[1]), "r"((av)[2]), "r"((av)[3]),            \
          "r"((bv)[0]), "r"((bv)[1]))

// block: 256 thr = 8 warps as 2(M) x 4(N); block tile 128x128; warp tile 64x32
template<bool SCORES>
__global__ void __launch_bounds__(256) gemm_tc_kernel(
    const float* __restrict__ A, const float* __restrict__ W,
    const float* __restrict__ a_src, const float* __restrict__ a_dst,
    float* __restrict__ out, float* __restrict__ ssrc, float* __restrict__ sdst)
{
    __shared__ float AsT[32][132];   // [k][m], tf32-converted
    __shared__ float Ws[32][132];    // [k][n], tf32-converted

    const int tid  = threadIdx.x;
    const int warp = tid >> 5, lane = tid & 31;
    const int g = lane >> 2, t = lane & 3;
    const int wm = warp >> 2;          // 0..1
    const int wn = warp & 3;           // 0..3 (== head for SCORES)
    const int m0 = wm * 64, n0 = wn * 32;
    const int row0 = blockIdx.x * 128;

    float acc[4][4][4];
#pragma unroll
    for (int i = 0; i < 4; ++i)
#pragma unroll
        for (int j = 0; j < 4; ++j)
#pragma unroll
            for (int k = 0; k < 4; ++k) acc[i][j][k] = 0.f;

    for (int kc = 0; kc < D; kc += 32) {
        // A chunk: 128 rows x 32 k -> AsT[k][m]
#pragma unroll
        for (int it = 0; it < 4; ++it) {
            int idx = tid + it * 256;    // 0..1023
            int r = idx >> 3;            // 0..127
            int q = idx & 7;             // k-quad
            int row = row0 + r;
            float4 v = make_float4(0.f, 0.f, 0.f, 0.f);
            if (row < NN) v = *(const float4*)&A[(long long)row * D + kc + q * 4];
            AsT[q * 4 + 0][r] = to_tf32(v.x);
            AsT[q * 4 + 1][r] = to_tf32(v.y);
            AsT[q * 4 + 2][r] = to_tf32(v.z);
            AsT[q * 4 + 3][r] = to_tf32(v.w);
        }
        // W chunk: 32 k x 128 n -> Ws[k][n]
#pragma unroll
        for (int it = 0; it < 4; ++it) {
            int idx = tid + it * 256;
            int kr = idx >> 5;           // 0..31
            int c4 = idx & 31;
            float4 v = *(const float4*)&W[(kc + kr) * D + c4 * 4];
            Ws[kr][c4 * 4 + 0] = to_tf32(v.x);
            Ws[kr][c4 * 4 + 1] = to_tf32(v.y);
            Ws[kr][c4 * 4 + 2] = to_tf32(v.z);
            Ws[kr][c4 * 4 + 3] = to_tf32(v.w);
        }
        __syncthreads();
#pragma unroll
        for (int ks = 0; ks < 32; ks += 8) {
            uint32_t a[4][4], b[4][2];
#pragma unroll
            for (int mt = 0; mt < 4; ++mt) {
                int mr = m0 + mt * 16 + g;
                a[mt][0] = __float_as_uint(AsT[ks + t][mr]);
                a[mt][1] = __float_as_uint(AsT[ks + t][mr + 8]);
                a[mt][2] = __float_as_uint(AsT[ks + t + 4][mr]);
                a[mt][3] = __float_as_uint(AsT[ks + t + 4][mr + 8]);
            }
#pragma unroll
            for (int nt = 0; nt < 4; ++nt) {
                int nc = n0 + nt * 8 + g;
                b[nt][0] = __float_as_uint(Ws[ks + t][nc]);
                b[nt][1] = __float_as_uint(Ws[ks + t + 4][nc]);
            }
#pragma unroll
            for (int mt = 0; mt < 4; ++mt)
#pragma unroll
                for (int nt = 0; nt < 4; ++nt)
                    MMA_TF32(acc[mt][nt], a[mt], b[nt]);
        }
        __syncthreads();
    }

    // epilogue: store out (+ fused attention scores)
    float2 asv[4], adv[4];
    if (SCORES) {
#pragma unroll
        for (int nt = 0; nt < 4; ++nt) {
            int c = nt * 8 + 2 * t;      // channel within head wn
            asv[nt] = make_float2(a_src[wn * CH + c], a_src[wn * CH + c + 1]);
            adv[nt] = make_float2(a_dst[wn * CH + c], a_dst[wn * CH + c + 1]);
        }
    }
#pragma unroll
    for (int mt = 0; mt < 4; ++mt) {
        int r_lo = row0 + m0 + mt * 16 + g;
        int r_hi = r_lo + 8;
        float su_lo = 0.f, du_lo = 0.f, su_hi = 0.f, du_hi = 0.f;
#pragma unroll
        for (int nt = 0; nt < 4; ++nt) {
            int col = n0 + nt * 8 + 2 * t;
            if (r_lo < NN)
                *(float2*)&out[(long long)r_lo * D + col] =
                    make_float2(acc[mt][nt][0], acc[mt][nt][1]);
            if (r_hi < NN)
                *(float2*)&out[(long long)r_hi * D + col] =
                    make_float2(acc[mt][nt][2], acc[mt][nt][3]);
            if (SCORES) {
                su_lo += acc[mt][nt][0] * asv[nt].x + acc[mt][nt][1] * asv[nt].y;
                du_lo += acc[mt][nt][0] * adv[nt].x + acc[mt][nt][1] * adv[nt].y;
                su_hi += acc[mt][nt][2] * asv[nt].x + acc[mt][nt][3] * asv[nt].y;
                du_hi += acc[mt][nt][2] * adv[nt].x + acc[mt][nt][3] * adv[nt].y;
            }
        }
        if (SCORES) {
#pragma unroll
            for (int off = 1; off <= 2; off <<= 1) {
                su_lo += __shfl_xor_sync(0xffffffffu, su_lo, off);
                du_lo += __shfl_xor_sync(0xffffffffu, du_lo, off);
                su_hi += __shfl_xor_sync(0xffffffffu, su_hi, off);
                du_hi += __shfl_xor_sync(0xffffffffu, du_hi, off);
            }
            if (t == 0) {
                if (r_lo < NN) { ssrc[r_lo * HEADS + wn] = su_lo; sdst[r_lo * HEADS + wn] = du_lo; }
                if (r_hi < NN) { ssrc[r_hi * HEADS + wn] = su_hi; sdst[r_hi * HEADS + wn] = du_hi; }
            }
        }
    }
}

// ---------------- softmax + aggregation -----------------------------------------
__device__ __forceinline__ float lrelu(float v) { return v > 0.f ? v : NEG_SLOPE * v; }

template<int LAYER>
__global__ void __launch_bounds__(256) agg_kernel(
    const float* __restrict__ h,
    const float* __restrict__ ss,
    const float* __restrict__ sd,
    const float* __restrict__ bias,
    float* __restrict__ out,
    const float* __restrict__ xr,
    const float* __restrict__ br)
{
    __shared__ float4 elc[8][CAP];
    __shared__ int    srcc[8][CAP];

    int warp = (blockIdx.x * blockDim.x + threadIdx.x) >> 5;
    int wip = (threadIdx.x >> 5);
    int lane = threadIdx.x & 31;
    if (warp >= NN) return;
    int n = warp;
    int begin = g_offs[n], end = g_offs[n + 1];
    int deg = end - begin;

    float4 sdv = *(const float4*)&sd[n * HEADS];

    float m0 = -1e30f, m1 = -1e30f, m2 = -1e30f, m3 = -1e30f;
    float d0 = 0.f, d1 = 0.f, d2 = 0.f, d3 = 0.f;

    if (deg <= CAP) {
        // pass 1: gather scores once, cache logits, track max
        for (int e = begin + lane; e < end; e += 32) {
            int s = g_sorted_src[e];
            float4 sv = *(const float4*)&ss[s * HEADS];
            float4 el = make_float4(lrelu(sv.x + sdv.x), lrelu(sv.y + sdv.y),
                                    lrelu(sv.z + sdv.z), lrelu(sv.w + sdv.w));
            elc[wip][e - begin] = el;
            srcc[wip][e - begin] = s;
            m0 = fmaxf(m0, el.x); m1 = fmaxf(m1, el.y);
            m2 = fmaxf(m2, el.z); m3 = fmaxf(m3, el.w);
        }
#pragma unroll
        for (int off = 16; off; off >>= 1) {
            m0 = fmaxf(m0, __shfl_xor_sync(0xffffffffu, m0, off));
            m1 = fmaxf(m1, __shfl_xor_sync(0xffffffffu, m1, off));
            m2 = fmaxf(m2, __shfl_xor_sync(0xffffffffu, m2, off));
            m3 = fmaxf(m3, __shfl_xor_sync(0xffffffffu, m3, off));
        }
        __syncwarp();
        // pass 2: denom from cached logits
        for (int i = lane; i < deg; i += 32) {
            float4 el = elc[wip][i];
            d0 += __expf(el.x - m0); d1 += __expf(el.y - m1);
            d2 += __expf(el.z - m2); d3 += __expf(el.w - m3);
        }
    } else {
        // fallback (statistically unreachable): global recompute
        for (int e = begin + lane; e < end; e += 32) {
            int s = g_sorted_src[e];
            float4 sv = *(const float4*)&ss[s * HEADS];
            m0 = fmaxf(m0, lrelu(sv.x + sdv.x)); m1 = fmaxf(m1, lrelu(sv.y + sdv.y));
            m2 = fmaxf(m2, lrelu(sv.z + sdv.z)); m3 = fmaxf(m3, lrelu(sv.w + sdv.w));
        }
#pragma unroll
        for (int off = 16; off; off >>= 1) {
            m0 = fmaxf(m0, __shfl_xor_sync(0xffffffffu, m0, off));
            m1 = fmaxf(m1, __shfl_xor_sync(0xffffffffu, m1, off));
            m2 = fmaxf(m2, __shfl_xor_sync(0xffffffffu, m2, off));
            m3 = fmaxf(m3, __shfl_xor_sync(0xffffffffu, m3, off));
        }
        for (int e = begin + lane; e < end; e += 32) {
            int s = g_sorted_src[e];
            float4 sv = *(const float4*)&ss[s * HEADS];
            d0 += __expf(lrelu(sv.x + sdv.x) - m0);
            d1 += __expf(lrelu(sv.y + sdv.y) - m1);
            d2 += __expf(lrelu(sv.z + sdv.z) - m2);
            d3 += __expf(lrelu(sv.w + sdv.w) - m3);
        }
    }
#pragma unroll
    for (int off = 16; off; off >>= 1) {
        d0 += __shfl_xor_sync(0xffffffffu, d0, off);
        d1 += __shfl_xor_sync(0xffffffffu, d1, off);
        d2 += __shfl_xor_sync(0xffffffffu, d2, off);
        d3 += __shfl_xor_sync(0xffffffffu, d3, off);
    }

    int hd = lane >> 3;
    int c0 = lane * 4;
    float mh  = (hd == 0) ? m0 : (hd == 1) ? m1 : (hd == 2) ? m2 : m3;
    float dh  = (hd == 0) ? d0 : (hd == 1) ? d1 : (hd == 2) ? d2 : d3;
    float sdh = (hd == 0) ? sdv.x : (hd == 1) ? sdv.y : (hd == 2) ? sdv.z : sdv.w;
    float inv_dh = 1.f / dh;

    float ax = 0.f, ay = 0.f, az = 0.f, aw = 0.f;
    if (deg <= CAP) {
#pragma unroll 4
        for (int i = 0; i < deg; ++i) {
            int s = srcc[wip][i];
            float4 el = elc[wip][i];
            float elh = (hd == 0) ? el.x : (hd == 1) ? el.y : (hd == 2) ? el.z : el.w;
            float alpha = __expf(elh - mh) * inv_dh;
            float4 hv = *(const float4*)&h[(long long)s * D + c0];
            ax += alpha * hv.x; ay += alpha * hv.y;
            az += alpha * hv.z; aw += alpha * hv.w;
        }
    } else {
        for (int e = begin; e < end; ++e) {
            int s = g_sorted_src[e];
            float alpha = __expf(lrelu(ss[s * HEADS + hd] + sdh) - mh) * inv_dh;
            float4 hv = *(const float4*)&h[(long long)s * D + c0];
            ax += alpha * hv.x; ay += alpha * hv.y;
            az += alpha * hv.z; aw += alpha * hv.w;
        }
    }

    float4 b = *(const float4*)&bias[c0];
    if (LAYER == 1) {
        float4 o = make_float4(fmaxf(ax + b.x, 0.f), fmaxf(ay + b.y, 0.f),
                               fmaxf(az + b.z, 0.f), fmaxf(aw + b.w, 0.f));
        *(float4*)&out[(long long)n * D + c0] = o;
    } else {
        float4 r  = *(const float4*)&xr[(long long)n * D + c0];
        float4 bb = *(const float4*)&br[c0];
        float4 o = make_float4(ax + b.x + r.x + bb.x, ay + b.y + r.y + bb.y,
                               az + b.z + r.z + bb.z, aw + b.w + r.w + bb.w);
        *(float4*)&out[(long long)n * D + c0] = o;
    }
}

// ---------------- launch --------------------------------------------------------
extern "C" void kernel_launch(void* const* d_in, const int* in_sizes, int n_in,
                              void* d_out, int out_size) {
    const float* x   = (const float*)d_in[0];
    const void*  ei  = d_in[1];
    const float* W1  = (const float*)d_in[2];
    const float* a1s = (const float*)d_in[3];
    const float* a1d = (const float*)d_in[4];
    const float* b1  = (const float*)d_in[5];
    const float* W2  = (const float*)d_in[6];
    const float* a2s = (const float*)d_in[7];
    const float* a2d = (const float*)d_in[8];
    const float* b2  = (const float*)d_in[9];
    const float* Wr  = (const float*)d_in[10];
    const float* br  = (const float*)d_in[11];
    float* out = (float*)d_out;

    float* bufA; cudaGetSymbolAddress((void**)&bufA, g_bufA);
    float* bufB; cudaGetSymbolAddress((void**)&bufB, g_bufB);
    float* xr;   cudaGetSymbolAddress((void**)&xr, g_xr);
    float* ssp;  cudaGetSymbolAddress((void**)&ssp, g_ss);
    float* sdp;  cudaGetSymbolAddress((void**)&sdp, g_sd);

    detect_kernel<<<1, 32>>>((const unsigned int*)ei);
    init_deg_kernel<<<(NN + 255) / 256, 256>>>();
    count_kernel<<<(EE + 255) / 256, 256>>>(ei);
    scan_k1<<<NB_SCAN, 256>>>();
    scan_k2<<<1, 128>>>();
    scan_k3<<<NB_SCAN, 256>>>();
    scatter_kernel<<<(ET + 255) / 256, 256>>>(ei);

    const int gemm_grid = (NN + 127) / 128;
    gemm_tc_kernel<true><<<gemm_grid, 256>>>(x, W1, a1s, a1d, bufA, ssp, sdp);
    gemm_tc_kernel<false><<<gemm_grid, 256>>>(x, Wr, nullptr, nullptr, xr, nullptr, nullptr);
    agg_kernel<1><<<(NN + 7) / 8, 256>>>(bufA, ssp, sdp, b1, bufB, nullptr, nullptr);
    gemm_tc_kernel<true><<<gemm_grid, 256>>>(bufB, W2, a2s, a2d, bufA, ssp, sdp);
    agg_kernel<2><<<(NN + 7) / 8, 256>>>(bufA, ssp, sdp, b2, out, xr, br);
}